// round 7
// baseline (speedup 1.0000x reference)
#include <cuda_runtime.h>
#include <cuda_bf16.h>

#define TT 512
#define LL 62
#define KK 64
#define NB 8            // batches per block
#define DST 4           // cp.async stages
#define US 66           // u_sh row stride (bf16 elems) — bank-spread padding
#define PS 66           // pred_sh row stride (floats)

__global__ void init_out_kernel(float* out) { out[0] = 0.0f; }

__device__ __forceinline__ unsigned pack_bf2(float lo, float hi) {
    __nv_bfloat162 p = __floats2bfloat162_rn(lo, hi);
    return *reinterpret_cast<unsigned*>(&p);
}

// D(16x8,f32) += A(16x16,bf16,row) @ B(16x8,bf16,col)
__device__ __forceinline__ void mma_bf16(float c[4], const unsigned a[4],
                                         unsigned b0, unsigned b1) {
    asm volatile(
        "mma.sync.aligned.m16n8k16.row.col.f32.bf16.bf16.f32 "
        "{%0,%1,%2,%3}, {%4,%5,%6,%7}, {%8,%9}, {%0,%1,%2,%3};"
        : "+f"(c[0]), "+f"(c[1]), "+f"(c[2]), "+f"(c[3])
        : "r"(a[0]), "r"(a[1]), "r"(a[2]), "r"(a[3]), "r"(b0), "r"(b1));
}

__device__ __forceinline__ void cp8(unsigned dst, const void* src) {
    asm volatile("cp.async.ca.shared.global [%0], [%1], 8;"
                 :: "r"(dst), "l"(src) : "memory");
}

__global__ __launch_bounds__(32) void crf_mma_kernel(
    const float* __restrict__ pred,      // [B, T, L]
    const int*   __restrict__ ref,       // [B, T]
    const int*   __restrict__ seq_len,   // [B]
    const float* __restrict__ trans,     // [K, K]
    float* __restrict__ out)
{
    const int b0 = blockIdx.x * NB;
    const int l  = threadIdx.x;
    const int g  = l >> 2;               // 0..7
    const int t4 = l & 3;                // 0..3
    const int n0 = 2 * t4, n1 = n0 + 1;  // this lane's two batch columns

    __shared__ float          pred_sh[DST][NB][PS];
    __shared__ __nv_bfloat16  u_sh[NB][US];
    __shared__ float          red_sh[NB];

    const int sl0 = __ldg(&seq_len[b0 + n0]);
    const int sl1 = __ldg(&seq_len[b0 + n1]);
    int mx = __ldg(&seq_len[b0 + (l & 7)]);
    #pragma unroll
    for (int off = 16; off; off >>= 1)
        mx = max(mx, __shfl_xor_sync(0xffffffffu, mx, off));
    const int smax = mx;

    // A fragments: W[j][k] = exp(trans[k][j]); rows 62,63 of trans -> exp = 0.
    unsigned A[4][4][4];
    #pragma unroll
    for (int mt = 0; mt < 4; ++mt) {
        const int r0 = 16 * mt + g, r1 = r0 + 8;
        #pragma unroll
        for (int kt = 0; kt < 4; ++kt) {
            const int k0 = 16 * kt + 2 * t4;
            A[mt][kt][0] = pack_bf2(__expf(trans[(k0    ) * KK + r0]),
                                    __expf(trans[(k0 + 1) * KK + r0]));
            A[mt][kt][1] = pack_bf2(__expf(trans[(k0    ) * KK + r1]),
                                    __expf(trans[(k0 + 1) * KK + r1]));
            A[mt][kt][2] = pack_bf2(__expf(trans[(k0 + 8) * KK + r0]),
                                    __expf(trans[(k0 + 9) * KK + r0]));
            A[mt][kt][3] = pack_bf2(__expf(trans[(k0 + 8) * KK + r1]),
                                    __expf(trans[(k0 + 9) * KK + r1]));
        }
    }

    // u = exp(alpha - c): labels 1 at c=-1000, states >=62 (incl. pad) = 0.
    for (int idx = l; idx < NB * US; idx += 32) {
        const int k = idx % US;
        u_sh[idx / US][k] = __float2bfloat16((k < LL) ? 1.0f : 0.0f);
    }
    float cacc0 = -1000.0f, cacc1 = -1000.0f;

    // cp.async staging of obs rows (t = 0..smax-1, always < TT)
    auto stage = [&](int t) {
        const int st = t & (DST - 1);
        for (int idx = l; idx < NB * 31; idx += 32) {
            const int n = idx / 31, w = idx - n * 31;
            const float* src = pred + ((size_t)(b0 + n) * TT + t) * LL + 2 * w;
            cp8((unsigned)__cvta_generic_to_shared(&pred_sh[st][n][2 * w]), src);
        }
    };
    #pragma unroll
    for (int t = 0; t < DST - 1; ++t) {
        if (t <= smax - 1) stage(t);
        asm volatile("cp.async.commit_group;" ::: "memory");
    }
    __syncwarp();

    for (int s = 1; s <= smax; ++s) {
        const int t = s - 1;
        {   // stage t+3 (empty commit keeps group numbering)
            const int tn = t + DST - 1;
            if (tn <= smax - 1) stage(tn);
            asm volatile("cp.async.commit_group;" ::: "memory");
        }

        __syncwarp();                        // prev step's STS visible
        unsigned Bf[4][2];
        #pragma unroll
        for (int kt = 0; kt < 4; ++kt) {     // k = 16kt + 2t4 (+1), n = g
            Bf[kt][0] = *(const unsigned*)&u_sh[g][16 * kt + n0];
            Bf[kt][1] = *(const unsigned*)&u_sh[g][16 * kt + n0 + 8];
        }
        asm volatile("cp.async.wait_group %0;" :: "n"(DST - 1) : "memory");
        __syncwarp();                        // all lanes' obs tile visible

        float C[4][4] = {};
        #pragma unroll
        for (int mt = 0; mt < 4; ++mt)
            #pragma unroll
            for (int kt = 0; kt < 4; ++kt)
                mma_bf16(C[mt], A[mt][kt], Bf[kt][0], Bf[kt][1]);

        const bool act0 = (s <= sl0), act1 = (s <= sl1);
        float r0f = 1.0f, r1f = 1.0f;
        if (((s & 3) == 1) && (s != 1)) {    // deferred renorm, per batch
            if (act0) { const float u0 = __bfloat162float(u_sh[n0][0]);
                        r0f = __frcp_rn(u0); cacc0 += __logf(u0); }
            if (act1) { const float u1 = __bfloat162float(u_sh[n1][0]);
                        r1f = __frcp_rn(u1); cacc1 += __logf(u1); }
        }

        const int st = t & (DST - 1);
        #pragma unroll
        for (int mt = 0; mt < 4; ++mt) {
            const int j0 = 16 * mt + g, j1 = j0 + 8;
            if (act0) {
                const float e0 = (j0 < LL) ? __expf(pred_sh[st][n0][j0]) * r0f : 0.0f;
                const float e1 = (j1 < LL) ? __expf(pred_sh[st][n0][j1]) * r0f : 0.0f;
                u_sh[n0][j0] = __float2bfloat16(e0 * C[mt][0]);
                u_sh[n0][j1] = __float2bfloat16(e1 * C[mt][2]);
            }
            if (act1) {
                const float e0 = (j0 < LL) ? __expf(pred_sh[st][n1][j0]) * r1f : 0.0f;
                const float e1 = (j1 < LL) ? __expf(pred_sh[st][n1][j1]) * r1f : 0.0f;
                u_sh[n1][j0] = __float2bfloat16(e0 * C[mt][1]);
                u_sh[n1][j1] = __float2bfloat16(e1 * C[mt][3]);
            }
        }
    }

    asm volatile("cp.async.wait_all;" ::: "memory");
    __syncwarp();

    // ---- boundary step: D = W @ U(frozen), log domain ----
    unsigned Bf[4][2];
    #pragma unroll
    for (int kt = 0; kt < 4; ++kt) {
        Bf[kt][0] = *(const unsigned*)&u_sh[g][16 * kt + n0];
        Bf[kt][1] = *(const unsigned*)&u_sh[g][16 * kt + n0 + 8];
    }
    float D[4][4] = {};
    #pragma unroll
    for (int mt = 0; mt < 4; ++mt)
        #pragma unroll
        for (int kt = 0; kt < 4; ++kt)
            mma_bf16(D[mt], A[mt][kt], Bf[kt][0], Bf[kt][1]);

    auto obsb = [&](int j, int sl, int bb) -> float {
        if (j < LL)
            return ((sl < TT) ? __ldg(&pred[((size_t)bb * TT + sl) * LL + j]) : 0.0f)
                   - 1000.0f;
        return (j == LL) ? -1000.0f : 0.0f;
    };

    float al0[8], al1[8];
    #pragma unroll
    for (int mt = 0; mt < 4; ++mt) {
        const int j0 = 16 * mt + g, j1 = j0 + 8;
        al0[2 * mt + 0] = obsb(j0, sl0, b0 + n0) + cacc0 + __logf(D[mt][0]);
        al0[2 * mt + 1] = obsb(j1, sl0, b0 + n0) + cacc0 + __logf(D[mt][2]);
        al1[2 * mt + 0] = obsb(j0, sl1, b0 + n1) + cacc1 + __logf(D[mt][1]);
        al1[2 * mt + 1] = obsb(j1, sl1, b0 + n1) + cacc1 + __logf(D[mt][3]);
    }

    // logsumexp per batch over its 8-lane group (lanes sharing t4) x 8 rows
    float M0 = al0[0], M1 = al1[0];
    #pragma unroll
    for (int i = 1; i < 8; ++i) { M0 = fmaxf(M0, al0[i]); M1 = fmaxf(M1, al1[i]); }
    #pragma unroll
    for (int off = 4; off <= 16; off <<= 1) {
        M0 = fmaxf(M0, __shfl_xor_sync(0xffffffffu, M0, off));
        M1 = fmaxf(M1, __shfl_xor_sync(0xffffffffu, M1, off));
    }
    float S0 = 0.0f, S1 = 0.0f;
    #pragma unroll
    for (int i = 0; i < 8; ++i) { S0 += __expf(al0[i] - M0); S1 += __expf(al1[i] - M1); }
    #pragma unroll
    for (int off = 4; off <= 16; off <<= 1) {
        S0 += __shfl_xor_sync(0xffffffffu, S0, off);
        S1 += __shfl_xor_sync(0xffffffffu, S1, off);
    }
    if (g == 0) {
        red_sh[n0] = M0 + __logf(S0);
        red_sh[n1] = M1 + __logf(S1);
    }
    __syncwarp();

    // ---- gold score, exact fp32 ----
    float gacc = 0.0f;
    for (int n = 0; n < NB; ++n) {
        const int bb = b0 + n;
        const int sln = __ldg(&seq_len[bb]);
        const float* gp = pred + (size_t)bb * TT * LL;
        const int*   gr = ref  + (size_t)bb * TT;
        for (int tt = l; tt < sln; tt += 32)
            gacc += __ldg(&gp[tt * LL + __ldg(&gr[tt])]);
        for (int tt = l; tt <= sln; tt += 32) {
            const int from = tt ? __ldg(&gr[tt - 1]) : LL;
            const int to   = (tt == sln) ? (LL + 1) : __ldg(&gr[tt]);
            gacc += __ldg(&trans[from * KK + to]);
        }
    }
    #pragma unroll
    for (int off = 16; off; off >>= 1)
        gacc += __shfl_xor_sync(0xffffffffu, gacc, off);

    if (l == 0) {
        float tot = 0.0f;
        #pragma unroll
        for (int n = 0; n < NB; ++n) tot += red_sh[n];
        atomicAdd(out, tot - gacc);
    }
}

extern "C" void kernel_launch(void* const* d_in, const int* in_sizes, int n_in,
                              void* d_out, int out_size)
{
    const float* pred    = (const float*)d_in[0];
    const int*   ref     = (const int*)d_in[1];
    const int*   seq_len = (const int*)d_in[2];
    const float* trans   = (const float*)d_in[3];
    float*       out     = (float*)d_out;

    const int B = in_sizes[2];   // 1024

    init_out_kernel<<<1, 1>>>(out);
    crf_mma_kernel<<<B / NB, 32>>>(pred, ref, seq_len, trans, out);
}

// round 8
// speedup vs baseline: 2.2407x; 2.2407x over previous
#include <cuda_runtime.h>
#include <cuda_bf16.h>

#define TT 512
#define LL 62
#define KK 64
#define GG 4
#define NTH 64

__global__ void init_out_kernel(float* out) { out[0] = 0.0f; }

__device__ __forceinline__ __nv_bfloat162 u32_as_bf2(unsigned int v) {
    __nv_bfloat162 r;
    *reinterpret_cast<unsigned int*>(&r) = v;
    return r;
}

// dot_j = sum_{k=0}^{63} u[k] * E[k][j], u in shared bf16, E column j in
// bf16x2 register pairs (rows 2p,2p+1). Rows 62,63 of E are exactly 0.
__device__ __forceinline__ float dot64h(const __nv_bfloat16* __restrict__ ubuf,
                                        const __nv_bfloat162* __restrict__ Epk) {
    const uint4* up = reinterpret_cast<const uint4*>(ubuf);
    __nv_bfloat162 z; *reinterpret_cast<unsigned int*>(&z) = 0u;
    __nv_bfloat162 a0 = z, a1 = z, a2 = z, a3 = z;
    #pragma unroll
    for (int q = 0; q < 8; ++q) {
        uint4 v = up[q];
        a0 = __hfma2(u32_as_bf2(v.x), Epk[4 * q + 0], a0);
        a1 = __hfma2(u32_as_bf2(v.y), Epk[4 * q + 1], a1);
        a2 = __hfma2(u32_as_bf2(v.z), Epk[4 * q + 2], a2);
        a3 = __hfma2(u32_as_bf2(v.w), Epk[4 * q + 3], a3);
    }
    __nv_bfloat162 s = __hadd2(__hadd2(a0, a1), __hadd2(a2, a3));
    float2 f = __bfloat1622float2(s);
    return f.x + f.y;
}

__global__ __launch_bounds__(NTH) void crf_forward_kernel(
    const float* __restrict__ pred,      // [B, T, L]
    const int*   __restrict__ ref,       // [B, T]
    const int*   __restrict__ seq_len,   // [B]
    const float* __restrict__ trans,     // [K, K]
    float* __restrict__ out)
{
    const int bA   = 2 * blockIdx.x;
    const int bB   = bA + 1;
    const int j    = threadIdx.x;
    const int lane = j & 31;
    const int wid  = j >> 5;

    __shared__ __align__(16) __nv_bfloat16 u_sh[2][2][KK];  // [batch][buf][col]
    __shared__ float redM[2][2], redS[2][2], redG[2];

    const float* predA = pred + (size_t)bA * TT * LL;
    const float* predB = pred + (size_t)bB * TT * LL;
    const int*   refA  = ref  + (size_t)bA * TT;
    const int*   refB  = ref  + (size_t)bB * TT;
    const int    slA   = seq_len[bA];
    const int    slB   = seq_len[bB];
    const int    smax  = max(slA, slB);

    // E column j as bf16x2 pairs, shared between both batches.
    __nv_bfloat162 Epk[KK / 2];
    #pragma unroll
    for (int p = 0; p < KK / 2; ++p) {
        float e0 = __expf(trans[(2 * p + 0) * KK + j]);
        float e1 = __expf(trans[(2 * p + 1) * KK + j]);
        Epk[p] = __floats2bfloat162_rn(e0, e1);
    }

    // u = exp(alpha - c); labels 1 at c=-1000, start/end 0.
    const __nv_bfloat16 uinit = __float2bfloat16((j < LL) ? 1.0f : 0.0f);
    u_sh[0][0][j] = uinit;
    u_sh[1][0][j] = uinit;
    float cA = -1000.0f, cB = -1000.0f;

    const bool is_lab = (j < LL);
    float eA0[GG], eA1[GG], eB0[GG], eB1[GG];   // eobs pipelines
    #pragma unroll
    for (int i = 0; i < GG; ++i) {
        eA0[i] = is_lab ? __expf(__ldg(&predA[i * LL + j])) : 0.0f;
        eA1[i] = is_lab ? __expf(__ldg(&predB[i * LL + j])) : 0.0f;
    }

    int cur = 0;
    int s = 1;
    while (s + GG <= smax + 1) {               // steps s..s+3
        #pragma unroll
        for (int i = 0; i < GG; ++i) {         // prefetch steps s+4..s+7
            const int row = s + GG - 1 + i;
            const bool ok = is_lab && (row < TT);
            eB0[i] = ok ? __expf(__ldg(&predA[row * LL + j])) : 0.0f;
            eB1[i] = ok ? __expf(__ldg(&predB[row * LL + j])) : 0.0f;
        }
        #pragma unroll
        for (int i = 0; i < GG; ++i) {
            const int ss = s + i;
            const bool actA = (ss <= slA), actB = (ss <= slB);
            __syncthreads();
            float scA = eA0[i], scB = eA1[i];
            if (i == 0 && s != 1) {            // deferred renorm every 4 steps
                if (actA) { const float u0 = __bfloat162float(u_sh[0][cur][0]);
                            scA *= __frcp_rn(u0); cA += __logf(u0); }
                if (actB) { const float u0 = __bfloat162float(u_sh[1][cur][0]);
                            scB *= __frcp_rn(u0); cB += __logf(u0); }
            }
            const float d0 = dot64h(u_sh[0][cur], Epk);
            const float d1 = dot64h(u_sh[1][cur], Epk);
            if (actA) u_sh[0][cur ^ 1][j] = __float2bfloat16(scA * d0);
            if (actB) u_sh[1][cur ^ 1][j] = __float2bfloat16(scB * d1);
            cur ^= 1;
        }
        #pragma unroll
        for (int i = 0; i < GG; ++i) { eA0[i] = eB0[i]; eA1[i] = eB1[i]; }
        s += GG;
    }

    const int rem = smax + 1 - s;              // 0..GG-1 remaining steps
    #pragma unroll
    for (int i = 0; i < GG - 1; ++i) {
        if (i >= rem) break;
        const int ss = s + i;
        const bool actA = (ss <= slA), actB = (ss <= slB);
        __syncthreads();
        float scA = eA0[i], scB = eA1[i];
        if (i == 0 && s != 1) {
            if (actA) { const float u0 = __bfloat162float(u_sh[0][cur][0]);
                        scA *= __frcp_rn(u0); cA += __logf(u0); }
            if (actB) { const float u0 = __bfloat162float(u_sh[1][cur][0]);
                        scB *= __frcp_rn(u0); cB += __logf(u0); }
        }
        const float d0 = dot64h(u_sh[0][cur], Epk);
        const float d1 = dot64h(u_sh[1][cur], Epk);
        if (actA) u_sh[0][cur ^ 1][j] = __float2bfloat16(scA * d0);
        if (actB) u_sh[1][cur ^ 1][j] = __float2bfloat16(scB * d1);
        cur ^= 1;
    }
    __syncthreads();

    // ---- boundary step (sl+1) in log domain; frozen u lives in buf[sl&1] ----
    const float dA = dot64h(u_sh[0][slA & 1], Epk);
    const float dB = dot64h(u_sh[1][slB & 1], Epk);
    float obA, obB;
    if (j < LL) {
        obA = ((slA < TT) ? predA[slA * LL + j] : 0.0f) - 1000.0f;
        obB = ((slB < TT) ? predB[slB * LL + j] : 0.0f) - 1000.0f;
    } else {
        obA = obB = (j == LL) ? -1000.0f : 0.0f;
    }
    const float alA = obA + cA + __logf(dA);
    const float alB = obB + cB + __logf(dB);

    // ---- logsumexp over 64 columns, both batches ----
    float v0 = alA, v1 = alB;
    #pragma unroll
    for (int off = 16; off; off >>= 1) {
        v0 = fmaxf(v0, __shfl_xor_sync(0xffffffffu, v0, off));
        v1 = fmaxf(v1, __shfl_xor_sync(0xffffffffu, v1, off));
    }
    if (lane == 0) { redM[0][wid] = v0; redM[1][wid] = v1; }
    __syncthreads();
    const float M0 = fmaxf(redM[0][0], redM[0][1]);
    const float M1 = fmaxf(redM[1][0], redM[1][1]);

    float e0 = __expf(alA - M0), e1 = __expf(alB - M1);
    #pragma unroll
    for (int off = 16; off; off >>= 1) {
        e0 += __shfl_xor_sync(0xffffffffu, e0, off);
        e1 += __shfl_xor_sync(0xffffffffu, e1, off);
    }
    if (lane == 0) { redS[0][wid] = e0; redS[1][wid] = e1; }
    __syncthreads();
    const float lse0 = M0 + __logf(redS[0][0] + redS[0][1]);
    const float lse1 = M1 + __logf(redS[1][0] + redS[1][1]);

    // ---- gold score, exact fp32, both batches ----
    float gold = 0.0f;
    for (int t = j; t < slA; t += NTH)
        gold += predA[t * LL + refA[t]];
    for (int t = j; t <= slA; t += NTH) {
        const int from = (t == 0)   ? LL       : refA[t - 1];
        const int to   = (t == slA) ? (LL + 1) : refA[t];
        gold += trans[from * KK + to];
    }
    for (int t = j; t < slB; t += NTH)
        gold += predB[t * LL + refB[t]];
    for (int t = j; t <= slB; t += NTH) {
        const int from = (t == 0)   ? LL       : refB[t - 1];
        const int to   = (t == slB) ? (LL + 1) : refB[t];
        gold += trans[from * KK + to];
    }
    #pragma unroll
    for (int off = 16; off; off >>= 1)
        gold += __shfl_xor_sync(0xffffffffu, gold, off);
    if (lane == 0) redG[wid] = gold;
    __syncthreads();
    const float gold_total = redG[0] + redG[1];

    if (j == 0)
        atomicAdd(out, (lse0 + lse1) - gold_total);
}

extern "C" void kernel_launch(void* const* d_in, const int* in_sizes, int n_in,
                              void* d_out, int out_size)
{
    const float* pred    = (const float*)d_in[0];
    const int*   ref     = (const int*)d_in[1];
    const int*   seq_len = (const int*)d_in[2];
    const float* trans   = (const float*)d_in[3];
    float*       out     = (float*)d_out;

    const int B = in_sizes[2];   // 1024

    init_out_kernel<<<1, 1>>>(out);
    crf_forward_kernel<<<B / 2, NTH>>>(pred, ref, seq_len, trans, out);
}

// round 9
// speedup vs baseline: 4.0603x; 1.8121x over previous
#include <cuda_runtime.h>
#include <cuda_bf16.h>

#define TT 512
#define LL 62
#define KK 64
#define GG 4
#define FULLM 0xffffffffu

__global__ void init_out_kernel(float* out) { out[0] = 0.0f; }

__device__ __forceinline__ unsigned bf2u(__nv_bfloat162 v) {
    return *reinterpret_cast<unsigned*>(&v);
}
__device__ __forceinline__ __nv_bfloat162 ubf2(unsigned v) {
    __nv_bfloat162 r;
    *reinterpret_cast<unsigned*>(&r) = v;
    return r;
}

// Per-warp dot: lane l returns (d[2l], d[2l+1]) where d_j = sum_k u[k]E[k][j].
// u is distributed: lane p holds (u[2p], u[2p+1]); states 62,63 excluded
// (their E rows are exp(-10000) = 0).
__device__ __forceinline__ float2 dot_shfl(unsigned p_u,
                                           const __nv_bfloat162* __restrict__ E0,
                                           const __nv_bfloat162* __restrict__ E1) {
    __nv_bfloat162 z = ubf2(0u);
    __nv_bfloat162 a0 = z, a1 = z, a2 = z, a3 = z;   // column 2l
    __nv_bfloat162 b0 = z, b1 = z, b2 = z, b3 = z;   // column 2l+1
    #pragma unroll
    for (int p = 0; p < 31; ++p) {
        const __nv_bfloat162 up = ubf2(__shfl_sync(FULLM, p_u, p));
        switch (p & 3) {
            case 0: a0 = __hfma2(up, E0[p], a0); b0 = __hfma2(up, E1[p], b0); break;
            case 1: a1 = __hfma2(up, E0[p], a1); b1 = __hfma2(up, E1[p], b1); break;
            case 2: a2 = __hfma2(up, E0[p], a2); b2 = __hfma2(up, E1[p], b2); break;
            default:a3 = __hfma2(up, E0[p], a3); b3 = __hfma2(up, E1[p], b3); break;
        }
    }
    const __nv_bfloat162 sa = __hadd2(__hadd2(a0, a1), __hadd2(a2, a3));
    const __nv_bfloat162 sb = __hadd2(__hadd2(b0, b1), __hadd2(b2, b3));
    const float2 fa = __bfloat1622float2(sa);
    const float2 fb = __bfloat1622float2(sb);
    return make_float2(fa.x + fa.y, fb.x + fb.y);
}

__global__ __launch_bounds__(32) void crf_warp_kernel(
    const float* __restrict__ pred,      // [B, T, L]
    const int*   __restrict__ ref,       // [B, T]
    const int*   __restrict__ seq_len,   // [B]
    const float* __restrict__ trans,     // [K, K]
    float* __restrict__ out)
{
    const int b    = blockIdx.x;
    const int lane = threadIdx.x;
    const int j0   = 2 * lane;           // this lane's two columns
    const int j1   = j0 + 1;

    const float* predb = pred + (size_t)b * TT * LL;
    const int*   refb  = ref  + (size_t)b * TT;
    const int    sl    = seq_len[b];

    // E k-pairs for columns j0, j1: E*[p] = (exp(tr[2p][j]), exp(tr[2p+1][j])),
    // p = 0..30 covers states 0..61 (rows 62,63 are zero and skipped).
    __nv_bfloat162 E0[31], E1[31];
    #pragma unroll
    for (int p = 0; p < 31; ++p) {
        E0[p] = __floats2bfloat162_rn(__expf(trans[(2 * p) * KK + j0]),
                                      __expf(trans[(2 * p + 1) * KK + j0]));
        E1[p] = __floats2bfloat162_rn(__expf(trans[(2 * p) * KK + j1]),
                                      __expf(trans[(2 * p + 1) * KK + j1]));
    }

    // u = exp(alpha - c); labels (cols 0..61 -> lanes 0..30) start at 1,
    // lane 31 (cols 62,63: start/end) at 0. c = -1000.
    unsigned p_u = bf2u(__floats2bfloat162_rn(lane < 31 ? 1.0f : 0.0f,
                                              lane < 31 ? 1.0f : 0.0f));
    float c = -1000.0f;

    const bool lab = (lane < 31);        // both cols are labels
    // obs pipeline: one float2 LDG per lane per step, one group ahead
    float2 obA[GG], obB[GG];
    #pragma unroll
    for (int i = 0; i < GG; ++i)
        obA[i] = lab ? __ldg((const float2*)&predb[i * LL + j0])
                     : make_float2(-1000.0f, -1000.0f);

    int s = 1;
    while (s + GG <= sl + 1) {           // steps s..s+GG-1, all emission steps
        #pragma unroll
        for (int i = 0; i < GG; ++i) {   // prefetch next group
            const int row = s + GG - 1 + i;
            obB[i] = (lab && row < TT) ? __ldg((const float2*)&predb[row * LL + j0])
                                       : make_float2(-1000.0f, -1000.0f);
        }
        #pragma unroll
        for (int i = 0; i < GG; ++i) {
            float sc = 1.0f;
            if (i == 0 && s != 1) {      // deferred renorm every GG steps
                const float u0 = __bfloat162float(
                    ubf2(__shfl_sync(FULLM, p_u, 0)).x);
                sc = __frcp_rn(u0);
                c += __logf(u0);
            }
            const float2 d  = dot_shfl(p_u, E0, E1);
            const float  e0 = __expf(obA[i].x) * sc;
            const float  e1 = __expf(obA[i].y) * sc;
            p_u = bf2u(__floats2bfloat162_rn(e0 * d.x, e1 * d.y));
        }
        #pragma unroll
        for (int i = 0; i < GG; ++i) obA[i] = obB[i];
        s += GG;
    }

    const int rem = sl + 1 - s;          // 0..GG-1 remaining emission steps
    #pragma unroll
    for (int i = 0; i < GG - 1; ++i) {
        if (i >= rem) break;
        float sc = 1.0f;
        if (i == 0 && s != 1) {
            const float u0 = __bfloat162float(ubf2(__shfl_sync(FULLM, p_u, 0)).x);
            sc = __frcp_rn(u0);
            c += __logf(u0);
        }
        const float2 d  = dot_shfl(p_u, E0, E1);
        const float  e0 = __expf(obA[i].x) * sc;
        const float  e1 = __expf(obA[i].y) * sc;
        p_u = bf2u(__floats2bfloat162_rn(e0 * d.x, e1 * d.y));
    }

    // ---- boundary step (sl+1) in log domain over all 64 columns ----
    const float2 dB = dot_shfl(p_u, E0, E1);
    float ob0, ob1;
    if (lab) {
        const float2 base = (sl < TT) ? __ldg((const float2*)&predb[sl * LL + j0])
                                      : make_float2(0.0f, 0.0f);
        ob0 = base.x - 1000.0f;
        ob1 = base.y - 1000.0f;
    } else {
        ob0 = -1000.0f;                  // start column 62
        ob1 = 0.0f;                      // end column 63
    }
    const float al0 = ob0 + c + __logf(dB.x);
    const float al1 = ob1 + c + __logf(dB.y);

    // ---- logsumexp over the 64 columns ----
    float m = fmaxf(al0, al1);
    #pragma unroll
    for (int off = 16; off; off >>= 1)
        m = fmaxf(m, __shfl_xor_sync(FULLM, m, off));
    float S = __expf(al0 - m) + __expf(al1 - m);
    #pragma unroll
    for (int off = 16; off; off >>= 1)
        S += __shfl_xor_sync(FULLM, S, off);
    const float lse = m + __logf(S);

    // ---- gold score, exact fp32 ----
    float gold = 0.0f;
    for (int t = lane; t < sl; t += 32)
        gold += predb[t * LL + refb[t]];
    for (int t = lane; t <= sl; t += 32) {
        const int from = (t == 0)  ? LL       : refb[t - 1];
        const int to   = (t == sl) ? (LL + 1) : refb[t];
        gold += trans[from * KK + to];
    }
    #pragma unroll
    for (int off = 16; off; off >>= 1)
        gold += __shfl_xor_sync(FULLM, gold, off);

    if (lane == 0)
        atomicAdd(out, lse - gold);
}

extern "C" void kernel_launch(void* const* d_in, const int* in_sizes, int n_in,
                              void* d_out, int out_size)
{
    const float* pred    = (const float*)d_in[0];
    const int*   ref     = (const int*)d_in[1];
    const int*   seq_len = (const int*)d_in[2];
    const float* trans   = (const float*)d_in[3];
    float*       out     = (float*)d_out;

    const int B = in_sizes[2];   // 1024

    init_out_kernel<<<1, 1>>>(out);
    crf_warp_kernel<<<B, 32>>>(pred, ref, seq_len, trans, out);
}